// round 1
// baseline (speedup 1.0000x reference)
#include <cuda_runtime.h>
#include <cstdint>

#define IN_F   256
#define OUT_F  64
#define TILE_R 64
#define KC     16
#define MAX_NODES_PAD 100032   // 100000 rounded up to 64

// Scratch for h = x @ W + b  (25.6 MB, device global per allocation rules)
__device__ float g_h[(size_t)MAX_NODES_PAD * OUT_F];

// ---------------------------------------------------------------------------
// Kernel 1: zero the output (harness poisons d_out with 0xAA)
// ---------------------------------------------------------------------------
__global__ void zero_kernel(float4* __restrict__ out, int n4) {
    int i = blockIdx.x * blockDim.x + threadIdx.x;
    if (i < n4) out[i] = make_float4(0.f, 0.f, 0.f, 0.f);
}

// ---------------------------------------------------------------------------
// Kernel 2: h = x @ W + b   (fp32, packed f32x2 FMA)
// Tile: 64 rows x 64 cols per block, 256 threads, 4x4 micro-tile per thread.
// Rows are packed in pairs into 64-bit regs; fma.rn.f32x2 doubles the fp32
// FMA rate vs FFMA-3reg (rt_SMSP 1 effective vs 2).
// ---------------------------------------------------------------------------
__global__ __launch_bounds__(256) void gemm_kernel(
    const float* __restrict__ x,   // [n, 256]
    const float* __restrict__ W,   // [256, 64]
    const float* __restrict__ b,   // [64]
    float* __restrict__ h,         // [n_pad, 64]
    int n_nodes)
{
    __shared__ float xs[KC][68];     // [k][row], padded: 68*4B = 272B = 17x16B, keeps
                                     // float4 alignment and spreads banks
    __shared__ float ws[KC][OUT_F];  // [k][col]

    const int tid = threadIdx.x;
    const int tx  = tid & 15;        // col group: cols 4*tx .. 4*tx+3
    const int ty  = tid >> 4;        // row group: rows 4*ty .. 4*ty+3
    const int row0 = blockIdx.x * TILE_R;

    // loader mapping for x: each thread loads one float4 of one row
    const int lr = tid >> 2;         // row within tile (0..63)
    const int lq = tid & 3;          // which float4 within the 16-wide k-chunk
    // loader mapping for W
    const int wk = tid >> 4;         // k within chunk (0..15)
    const int wc = (tid & 15) * 4;   // col

    // accumulators: [row-pair][col], each holds 2 rows packed as f32x2
    unsigned long long acc[2][4];
#pragma unroll
    for (int p = 0; p < 2; ++p)
#pragma unroll
        for (int c = 0; c < 4; ++c) acc[p][c] = 0ull;

    for (int kc = 0; kc < IN_F; kc += KC) {
        // stage x chunk (transposed to [k][row])
        {
            const int grow = row0 + lr;
            float4 xv = make_float4(0.f, 0.f, 0.f, 0.f);
            if (grow < n_nodes)
                xv = *reinterpret_cast<const float4*>(&x[(size_t)grow * IN_F + kc + 4 * lq]);
            xs[4 * lq + 0][lr] = xv.x;
            xs[4 * lq + 1][lr] = xv.y;
            xs[4 * lq + 2][lr] = xv.z;
            xs[4 * lq + 3][lr] = xv.w;
        }
        // stage W chunk
        {
            float4 wv = *reinterpret_cast<const float4*>(&W[(size_t)(kc + wk) * OUT_F + wc]);
            *reinterpret_cast<float4*>(&ws[wk][wc]) = wv;
        }
        __syncthreads();

#pragma unroll
        for (int k = 0; k < KC; ++k) {
            float4 wv = *reinterpret_cast<const float4*>(&ws[k][tx * 4]);
            float4 xv = *reinterpret_cast<const float4*>(&xs[k][ty * 4]);

            unsigned long long xa, xb, wd[4];
            asm("mov.b64 %0, {%1, %2};" : "=l"(xa) : "f"(xv.x), "f"(xv.y));
            asm("mov.b64 %0, {%1, %2};" : "=l"(xb) : "f"(xv.z), "f"(xv.w));
            asm("mov.b64 %0, {%1, %1};" : "=l"(wd[0]) : "f"(wv.x));
            asm("mov.b64 %0, {%1, %1};" : "=l"(wd[1]) : "f"(wv.y));
            asm("mov.b64 %0, {%1, %1};" : "=l"(wd[2]) : "f"(wv.z));
            asm("mov.b64 %0, {%1, %1};" : "=l"(wd[3]) : "f"(wv.w));
#pragma unroll
            for (int c = 0; c < 4; ++c) {
                asm("fma.rn.f32x2 %0, %1, %2, %0;" : "+l"(acc[0][c]) : "l"(xa), "l"(wd[c]));
                asm("fma.rn.f32x2 %0, %1, %2, %0;" : "+l"(acc[1][c]) : "l"(xb), "l"(wd[c]));
            }
        }
        __syncthreads();
    }

    // epilogue: unpack, add bias, store h rows
    float4 bv = *reinterpret_cast<const float4*>(&b[tx * 4]);
#pragma unroll
    for (int p = 0; p < 2; ++p) {
        float lo[4], hi[4];
#pragma unroll
        for (int c = 0; c < 4; ++c)
            asm("mov.b64 {%0, %1}, %2;" : "=f"(lo[c]), "=f"(hi[c]) : "l"(acc[p][c]));
        const int r_lo = row0 + ty * 4 + 2 * p;
        const int r_hi = r_lo + 1;
        if (r_lo < n_nodes) {
            float4 v = make_float4(lo[0] + bv.x, lo[1] + bv.y, lo[2] + bv.z, lo[3] + bv.w);
            *reinterpret_cast<float4*>(&h[(size_t)r_lo * OUT_F + tx * 4]) = v;
        }
        if (r_hi < n_nodes) {
            float4 v = make_float4(hi[0] + bv.x, hi[1] + bv.y, hi[2] + bv.z, hi[3] + bv.w);
            *reinterpret_cast<float4*>(&h[(size_t)r_hi * OUT_F + tx * 4]) = v;
        }
    }
}

// ---------------------------------------------------------------------------
// Kernel 3: scatter  out[dst] += w * h[src]
// 16 lanes per edge; each lane handles one float4 (16B) of the 64-float row.
// h is L2-resident (25.6 MB); atomics use vector red (no return) to quarter
// the L2 atomic op count.
// ---------------------------------------------------------------------------
__global__ __launch_bounds__(256) void scatter_kernel(
    const int*   __restrict__ src,
    const int*   __restrict__ dst,
    const float* __restrict__ ew,
    const float* __restrict__ h,
    float*       __restrict__ out,
    int n_edges)
{
    const int idx = blockIdx.x * blockDim.x + threadIdx.x;
    const int e    = idx >> 4;
    const int comp = idx & 15;
    if (e >= n_edges) return;

    const int   s  = src[e];
    const int   d  = dst[e];
    const float wt = ew[e];

    float4 hv = *reinterpret_cast<const float4*>(&h[(size_t)s * OUT_F + comp * 4]);
    float4 m  = make_float4(hv.x * wt, hv.y * wt, hv.z * wt, hv.w * wt);

    float* p = &out[(size_t)d * OUT_F + comp * 4];
    asm volatile("red.global.add.v4.f32 [%0], {%1, %2, %3, %4};"
                 :: "l"(p), "f"(m.x), "f"(m.y), "f"(m.z), "f"(m.w)
                 : "memory");
}

// ---------------------------------------------------------------------------
extern "C" void kernel_launch(void* const* d_in, const int* in_sizes, int n_in,
                              void* d_out, int out_size)
{
    const float* x   = (const float*)d_in[0];
    const int*   es  = (const int*)  d_in[1];
    const int*   ed  = (const int*)  d_in[2];
    const float* ew  = (const float*)d_in[3];
    const float* W   = (const float*)d_in[4];
    const float* b   = (const float*)d_in[5];
    float*       out = (float*)d_out;

    const int n_nodes = in_sizes[0] / IN_F;
    const int n_edges = in_sizes[1];

    float* h;
    cudaGetSymbolAddress((void**)&h, g_h);

    // 1) zero output
    {
        const int n4 = out_size / 4;
        zero_kernel<<<(n4 + 255) / 256, 256>>>((float4*)out, n4);
    }
    // 2) h = x @ W + b
    {
        const int nblk = (n_nodes + TILE_R - 1) / TILE_R;
        gemm_kernel<<<nblk, 256>>>(x, W, b, h, n_nodes);
    }
    // 3) out[dst] += w * h[src]
    {
        const long long total = (long long)n_edges * 16;
        const int nblk = (int)((total + 255) / 256);
        scatter_kernel<<<nblk, 256>>>(es, ed, ew, h, out, n_edges);
    }
}

// round 2
// speedup vs baseline: 1.2016x; 1.2016x over previous
#include <cuda_runtime.h>
#include <cstdint>

#define IN_F   256
#define OUT_F  64
#define TILE_R 64
#define KC     16

#define MAX_NODES 100000
#define MAX_EDGES 1600000
#define SCAN_BS   256
#define NB        392                 // ceil(100000/256)
#define NT        (NB * SCAN_BS)      // 100352 padded node count

// ---------------- device scratch (static allocation per harness rules) -----
__device__ float g_h[(size_t)MAX_NODES * OUT_F];   // h = xW + b   (25.6 MB)
__device__ int   g_counts[NT];
__device__ int   g_starts[NT];
__device__ int   g_cursor[NT];
__device__ int   g_bsum[NB];
__device__ int   g_boff[NB];
__device__ int2  g_edges[MAX_EDGES];               // packed (src, w_bits), dst-sorted

// ---------------------------------------------------------------------------
// CSR build: zero counts -> histogram(dst) -> 3-pass exclusive scan -> fill
// ---------------------------------------------------------------------------
__global__ void zero_counts_kernel() {
    int i = blockIdx.x * blockDim.x + threadIdx.x;
    if (i < NT) g_counts[i] = 0;
}

__global__ void hist_kernel(const int* __restrict__ dst, int n_edges) {
    int e = blockIdx.x * blockDim.x + threadIdx.x;
    if (e < n_edges) atomicAdd(&g_counts[dst[e]], 1);
}

// pass A: per-256 tile exclusive scan, emit tile totals
__global__ void scanA_kernel() {
    __shared__ int s[SCAN_BS];
    const int t = threadIdx.x, b = blockIdx.x, i = b * SCAN_BS + t;
    const int v = g_counts[i];
    s[t] = v;
    __syncthreads();
#pragma unroll
    for (int off = 1; off < SCAN_BS; off <<= 1) {
        int u = (t >= off) ? s[t - off] : 0;
        __syncthreads();
        s[t] += u;
        __syncthreads();
    }
    g_starts[i] = s[t] - v;                 // exclusive within tile
    if (t == SCAN_BS - 1) g_bsum[b] = s[t]; // tile total
}

// pass B: single block scans NB tile totals (padded to 512)
__global__ void scanB_kernel() {
    __shared__ int s[512];
    const int t = threadIdx.x;
    const int v = (t < NB) ? g_bsum[t] : 0;
    s[t] = v;
    __syncthreads();
#pragma unroll
    for (int off = 1; off < 512; off <<= 1) {
        int u = (t >= off) ? s[t - off] : 0;
        __syncthreads();
        s[t] += u;
        __syncthreads();
    }
    if (t < NB) g_boff[t] = s[t] - v;       // exclusive tile offset
}

// pass C: add tile offsets, init fill cursors
__global__ void scanC_kernel() {
    int i = blockIdx.x * blockDim.x + threadIdx.x;
    if (i < NT) {
        int st = g_starts[i] + g_boff[i / SCAN_BS];
        g_starts[i] = st;
        g_cursor[i] = st;
    }
}

__global__ void fill_kernel(const int* __restrict__ src,
                            const int* __restrict__ dst,
                            const float* __restrict__ ew,
                            int n_edges) {
    int e = blockIdx.x * blockDim.x + threadIdx.x;
    if (e >= n_edges) return;
    int d = dst[e];
    int p = atomicAdd(&g_cursor[d], 1);
    g_edges[p] = make_int2(src[e], __float_as_int(ew[e]));
}

// ---------------------------------------------------------------------------
// GEMM: h = x @ W + b  (fp32, packed fma.rn.f32x2 — 2x FFMA rate)
// 64x64 tile per 256-thread block, 4x4 micro-tile per thread.
// ---------------------------------------------------------------------------
__global__ __launch_bounds__(256) void gemm_kernel(
    const float* __restrict__ x,
    const float* __restrict__ W,
    const float* __restrict__ b,
    int n_nodes)
{
    __shared__ float xs[KC][68];
    __shared__ float ws[KC][OUT_F];

    const int tid = threadIdx.x;
    const int tx  = tid & 15;
    const int ty  = tid >> 4;
    const int row0 = blockIdx.x * TILE_R;

    const int lr = tid >> 2;
    const int lq = tid & 3;
    const int wk = tid >> 4;
    const int wc = (tid & 15) * 4;

    unsigned long long acc[2][4];
#pragma unroll
    for (int p = 0; p < 2; ++p)
#pragma unroll
        for (int c = 0; c < 4; ++c) acc[p][c] = 0ull;

    for (int kc = 0; kc < IN_F; kc += KC) {
        {
            const int grow = row0 + lr;
            float4 xv = make_float4(0.f, 0.f, 0.f, 0.f);
            if (grow < n_nodes)
                xv = *reinterpret_cast<const float4*>(&x[(size_t)grow * IN_F + kc + 4 * lq]);
            xs[4 * lq + 0][lr] = xv.x;
            xs[4 * lq + 1][lr] = xv.y;
            xs[4 * lq + 2][lr] = xv.z;
            xs[4 * lq + 3][lr] = xv.w;
        }
        {
            float4 wv = *reinterpret_cast<const float4*>(&W[(size_t)(kc + wk) * OUT_F + wc]);
            *reinterpret_cast<float4*>(&ws[wk][wc]) = wv;
        }
        __syncthreads();

#pragma unroll
        for (int k = 0; k < KC; ++k) {
            float4 wv = *reinterpret_cast<const float4*>(&ws[k][tx * 4]);
            float4 xv = *reinterpret_cast<const float4*>(&xs[k][ty * 4]);

            unsigned long long xa, xb, wd[4];
            asm("mov.b64 %0, {%1, %2};" : "=l"(xa) : "f"(xv.x), "f"(xv.y));
            asm("mov.b64 %0, {%1, %2};" : "=l"(xb) : "f"(xv.z), "f"(xv.w));
            asm("mov.b64 %0, {%1, %1};" : "=l"(wd[0]) : "f"(wv.x));
            asm("mov.b64 %0, {%1, %1};" : "=l"(wd[1]) : "f"(wv.y));
            asm("mov.b64 %0, {%1, %1};" : "=l"(wd[2]) : "f"(wv.z));
            asm("mov.b64 %0, {%1, %1};" : "=l"(wd[3]) : "f"(wv.w));
#pragma unroll
            for (int c = 0; c < 4; ++c) {
                asm("fma.rn.f32x2 %0, %1, %2, %0;" : "+l"(acc[0][c]) : "l"(xa), "l"(wd[c]));
                asm("fma.rn.f32x2 %0, %1, %2, %0;" : "+l"(acc[1][c]) : "l"(xb), "l"(wd[c]));
            }
        }
        __syncthreads();
    }

    float4 bv = *reinterpret_cast<const float4*>(&b[tx * 4]);
#pragma unroll
    for (int p = 0; p < 2; ++p) {
        float lo[4], hi[4];
#pragma unroll
        for (int c = 0; c < 4; ++c)
            asm("mov.b64 {%0, %1}, %2;" : "=f"(lo[c]), "=f"(hi[c]) : "l"(acc[p][c]));
        const int r_lo = row0 + ty * 4 + 2 * p;
        const int r_hi = r_lo + 1;
        if (r_lo < n_nodes) {
            float4 v = make_float4(lo[0] + bv.x, lo[1] + bv.y, lo[2] + bv.z, lo[3] + bv.w);
            *reinterpret_cast<float4*>(&g_h[(size_t)r_lo * OUT_F + tx * 4]) = v;
        }
        if (r_hi < n_nodes) {
            float4 v = make_float4(hi[0] + bv.x, hi[1] + bv.y, hi[2] + bv.z, hi[3] + bv.w);
            *reinterpret_cast<float4*>(&g_h[(size_t)r_hi * OUT_F + tx * 4]) = v;
        }
    }
}

// ---------------------------------------------------------------------------
// Gather: out[r] = sum_{e in CSR row r} w_e * h[src_e]   — no atomics.
// 16 lanes per row; lane owns one float4 of the 64-wide row. 2-wide software
// pipeline on the (edge, h-row) dependent load chain.
// ---------------------------------------------------------------------------
__global__ __launch_bounds__(256) void gather_kernel(
    float* __restrict__ out, int n_nodes)
{
    const int idx  = blockIdx.x * blockDim.x + threadIdx.x;
    const int row  = idx >> 4;
    const int lane = idx & 15;
    if (row >= n_nodes) return;

    const int start = g_starts[row];
    const int end   = start + g_counts[row];

    float4 acc = make_float4(0.f, 0.f, 0.f, 0.f);
    int j = start;

    // unrolled-by-2: two independent edge->h load chains in flight
    for (; j + 2 <= end; j += 2) {
        int2 ea = g_edges[j];
        int2 eb = g_edges[j + 1];
        float4 ha = *reinterpret_cast<const float4*>(&g_h[(size_t)ea.x * OUT_F + lane * 4]);
        float4 hb = *reinterpret_cast<const float4*>(&g_h[(size_t)eb.x * OUT_F + lane * 4]);
        float wa = __int_as_float(ea.y);
        float wb = __int_as_float(eb.y);
        acc.x += wa * ha.x;  acc.y += wa * ha.y;
        acc.z += wa * ha.z;  acc.w += wa * ha.w;
        acc.x += wb * hb.x;  acc.y += wb * hb.y;
        acc.z += wb * hb.z;  acc.w += wb * hb.w;
    }
    if (j < end) {
        int2 e = g_edges[j];
        float4 hv = *reinterpret_cast<const float4*>(&g_h[(size_t)e.x * OUT_F + lane * 4]);
        float w = __int_as_float(e.y);
        acc.x += w * hv.x;  acc.y += w * hv.y;
        acc.z += w * hv.z;  acc.w += w * hv.w;
    }

    *reinterpret_cast<float4*>(&out[(size_t)row * OUT_F + lane * 4]) = acc;
}

// ---------------------------------------------------------------------------
extern "C" void kernel_launch(void* const* d_in, const int* in_sizes, int n_in,
                              void* d_out, int out_size)
{
    const float* x   = (const float*)d_in[0];
    const int*   es  = (const int*)  d_in[1];
    const int*   ed  = (const int*)  d_in[2];
    const float* ew  = (const float*)d_in[3];
    const float* W   = (const float*)d_in[4];
    const float* b   = (const float*)d_in[5];
    float*       out = (float*)d_out;

    const int n_nodes = in_sizes[0] / IN_F;
    const int n_edges = in_sizes[1];

    const int eblk = (n_edges + 255) / 256;

    // GEMM first (independent of CSR build; overlaps nothing on one stream but
    // keeps the dependent chain tight before gather)
    gemm_kernel<<<(n_nodes + TILE_R - 1) / TILE_R, 256>>>(x, W, b, n_nodes);

    // CSR build
    zero_counts_kernel<<<NB, SCAN_BS>>>();
    hist_kernel<<<eblk, 256>>>(ed, n_edges);
    scanA_kernel<<<NB, SCAN_BS>>>();
    scanB_kernel<<<1, 512>>>();
    scanC_kernel<<<NB, SCAN_BS>>>();
    fill_kernel<<<eblk, 256>>>(es, ed, ew, n_edges);

    // Gather (writes every output row exactly once — no zero pass needed)
    gather_kernel<<<(n_nodes * 16 + 255) / 256, 256>>>(out, n_nodes);
}

// round 4
// speedup vs baseline: 1.4878x; 1.2382x over previous
#include <cuda_runtime.h>
#include <cuda_bf16.h>
#include <cstdint>

#define IN_F   256
#define OUT_F  64

#define MAX_NODES 100000
#define MAX_EDGES 1600000
#define SCAN_BS   256
#define NB        392                 // ceil(100000/256)
#define NT        (NB * SCAN_BS)      // 100352 padded node count

// ---------------- device scratch (static allocation per harness rules) -----
__device__ float g_h[(size_t)MAX_NODES * OUT_F];   // h = xW + b   (25.6 MB)
__device__ int   g_counts[NT];
__device__ int   g_starts[NT];
__device__ int   g_cursor[NT];
__device__ int   g_bsum[NB];
__device__ int   g_boff[NB];
__device__ int2  g_edges[MAX_EDGES];               // packed (src, w_bits), dst-grouped

// ===========================================================================
// GEMM: h = x @ W + b  via mma.sync m16n8k16 bf16 (3-term split: hh+hl+lh)
// Block: 256 threads (8 warps). Tile M=128 x N=64, K in 4 chunks of 64.
// ===========================================================================
#define TILE_M   128
#define KCHUNK   64
#define XS_PITCH 68                    // floats; 272B rows, float4-aligned, <=2-way conflicts
#define WB_PITCH 72                    // bf16;   conflict-free B-frag loads
#define SM_XS    0                                   // [128][68] f32 = 34816 B
#define SM_WH    (TILE_M * XS_PITCH * 4)             // [64][72] bf16 = 9216 B
#define SM_WL    (SM_WH + OUT_F * WB_PITCH * 2)
#define SM_BIAS  (SM_WL + OUT_F * WB_PITCH * 2)      // 53248
#define SM_TOTAL (SM_BIAS + OUT_F * 4)               // 53504 B

#define MMA16816(c, a, b0, b1) \
    asm volatile("mma.sync.aligned.m16n8k16.row.col.f32.bf16.bf16.f32 " \
        "{%0,%1,%2,%3}, {%4,%5,%6,%7}, {%8,%9}, {%0,%1,%2,%3};" \
        : "+f"((c)[0]), "+f"((c)[1]), "+f"((c)[2]), "+f"((c)[3]) \
        : "r"((a)[0]), "r"((a)[1]), "r"((a)[2]), "r"((a)[3]), "r"(b0), "r"(b1))

__device__ __forceinline__ void split2(float vx, float vy, uint32_t& hi, uint32_t& lo) {
    __nv_bfloat16 h0 = __float2bfloat16(vx);
    __nv_bfloat16 h1 = __float2bfloat16(vy);
    __nv_bfloat16 l0 = __float2bfloat16(vx - __bfloat162float(h0));
    __nv_bfloat16 l1 = __float2bfloat16(vy - __bfloat162float(h1));
    __nv_bfloat162 hp(h0, h1), lp(l0, l1);
    hi = *reinterpret_cast<uint32_t*>(&hp);
    lo = *reinterpret_cast<uint32_t*>(&lp);
}

__global__ __launch_bounds__(256) void gemm_mma_kernel(
    const float* __restrict__ x,
    const float* __restrict__ W,
    const float* __restrict__ b,
    int n_nodes)
{
    extern __shared__ char smem[];
    float*         xs = reinterpret_cast<float*>(smem + SM_XS);
    __nv_bfloat16* Wh = reinterpret_cast<__nv_bfloat16*>(smem + SM_WH);
    __nv_bfloat16* Wl = reinterpret_cast<__nv_bfloat16*>(smem + SM_WL);
    float*         bs = reinterpret_cast<float*>(smem + SM_BIAS);

    const int tid  = threadIdx.x;
    const int wid  = tid >> 5;
    const int lane = tid & 31;
    const int row0 = blockIdx.x * TILE_M;
    const int wm   = wid * 16;                 // warp's row base within tile
    const int lr   = lane >> 2;                // 0..7
    const int lq   = lane & 3;                 // 0..3

    if (tid < OUT_F) bs[tid] = b[tid];

    float acc[8][4];
#pragma unroll
    for (int nt = 0; nt < 8; ++nt)
#pragma unroll
        for (int i = 0; i < 4; ++i) acc[nt][i] = 0.f;

    for (int c = 0; c < 4; ++c) {
        __syncthreads();   // protect smem reuse from previous chunk

        // stage x chunk: 128 rows x 64 floats (coalesced float4)
        for (int i = tid; i < TILE_M * (KCHUNK / 4); i += 256) {
            const int r = i >> 4, q = i & 15;
            float4 v = make_float4(0.f, 0.f, 0.f, 0.f);
            const int grow = row0 + r;
            if (grow < n_nodes)
                v = *reinterpret_cast<const float4*>(&x[(size_t)grow * IN_F + c * KCHUNK + q * 4]);
            *reinterpret_cast<float4*>(&xs[r * XS_PITCH + q * 4]) = v;
        }
        // stage W chunk transposed + split: Wb[n][k]
        for (int i = tid; i < KCHUNK * OUT_F; i += 256) {
            const int k = i >> 6, n = i & 63;
            const float v = W[(size_t)(c * KCHUNK + k) * OUT_F + n];
            __nv_bfloat16 hi = __float2bfloat16(v);
            __nv_bfloat16 lo = __float2bfloat16(v - __bfloat162float(hi));
            Wh[n * WB_PITCH + k] = hi;
            Wl[n * WB_PITCH + k] = lo;
        }
        __syncthreads();

#pragma unroll
        for (int ks = 0; ks < 4; ++ks) {
            const int kk = ks * 16 + lq * 2;
            const int r  = wm + lr;
            float2 x0 = *reinterpret_cast<const float2*>(&xs[r * XS_PITCH + kk]);
            float2 x1 = *reinterpret_cast<const float2*>(&xs[(r + 8) * XS_PITCH + kk]);
            float2 x2 = *reinterpret_cast<const float2*>(&xs[r * XS_PITCH + kk + 8]);
            float2 x3 = *reinterpret_cast<const float2*>(&xs[(r + 8) * XS_PITCH + kk + 8]);

            uint32_t ah[4], al[4];
            split2(x0.x, x0.y, ah[0], al[0]);
            split2(x1.x, x1.y, ah[1], al[1]);
            split2(x2.x, x2.y, ah[2], al[2]);
            split2(x3.x, x3.y, ah[3], al[3]);

#pragma unroll
            for (int nt = 0; nt < 8; ++nt) {
                const int n = nt * 8 + lr;
                const uint32_t bh0 = *reinterpret_cast<const uint32_t*>(&Wh[n * WB_PITCH + kk]);
                const uint32_t bh1 = *reinterpret_cast<const uint32_t*>(&Wh[n * WB_PITCH + kk + 8]);
                const uint32_t bl0 = *reinterpret_cast<const uint32_t*>(&Wl[n * WB_PITCH + kk]);
                const uint32_t bl1 = *reinterpret_cast<const uint32_t*>(&Wl[n * WB_PITCH + kk + 8]);
                MMA16816(acc[nt], ah, bh0, bh1);
                MMA16816(acc[nt], ah, bl0, bl1);
                MMA16816(acc[nt], al, bh0, bh1);
            }
        }
    }

    // epilogue: add bias, store float2 pairs
    const int r_lo = row0 + wm + lr;
    const int r_hi = r_lo + 8;
#pragma unroll
    for (int nt = 0; nt < 8; ++nt) {
        const int col = nt * 8 + lq * 2;
        const float b0 = bs[col], b1 = bs[col + 1];
        if (r_lo < n_nodes) {
            float2 v = make_float2(acc[nt][0] + b0, acc[nt][1] + b1);
            *reinterpret_cast<float2*>(&g_h[(size_t)r_lo * OUT_F + col]) = v;
        }
        if (r_hi < n_nodes) {
            float2 v = make_float2(acc[nt][2] + b0, acc[nt][3] + b1);
            *reinterpret_cast<float2*>(&g_h[(size_t)r_hi * OUT_F + col]) = v;
        }
    }
}

// ===========================================================================
// CSR build: zero counts -> histogram(dst) -> 3-pass exclusive scan -> fill
// ===========================================================================
__global__ void zero_counts_kernel() {
    int i = blockIdx.x * blockDim.x + threadIdx.x;
    if (i < NT) g_counts[i] = 0;
}

__global__ void hist_kernel(const int* __restrict__ dst, int n_edges) {
    int e = blockIdx.x * blockDim.x + threadIdx.x;
    if (e < n_edges) atomicAdd(&g_counts[dst[e]], 1);
}

__global__ void scanA_kernel() {
    __shared__ int s[SCAN_BS];
    const int t = threadIdx.x, blk = blockIdx.x, i = blk * SCAN_BS + t;
    const int v = g_counts[i];
    s[t] = v;
    __syncthreads();
#pragma unroll
    for (int off = 1; off < SCAN_BS; off <<= 1) {
        int u = (t >= off) ? s[t - off] : 0;
        __syncthreads();
        s[t] += u;
        __syncthreads();
    }
    g_starts[i] = s[t] - v;
    if (t == SCAN_BS - 1) g_bsum[blk] = s[t];
}

__global__ void scanB_kernel() {
    __shared__ int s[512];
    const int t = threadIdx.x;
    const int v = (t < NB) ? g_bsum[t] : 0;
    s[t] = v;
    __syncthreads();
#pragma unroll
    for (int off = 1; off < 512; off <<= 1) {
        int u = (t >= off) ? s[t - off] : 0;
        __syncthreads();
        s[t] += u;
        __syncthreads();
    }
    if (t < NB) g_boff[t] = s[t] - v;
}

__global__ void scanC_kernel() {
    int i = blockIdx.x * blockDim.x + threadIdx.x;
    if (i < NT) {
        int st = g_starts[i] + g_boff[i / SCAN_BS];
        g_starts[i] = st;
        g_cursor[i] = st;
    }
}

__global__ void fill_kernel(const int* __restrict__ src,
                            const int* __restrict__ dst,
                            const float* __restrict__ ew,
                            int n_edges) {
    int e = blockIdx.x * blockDim.x + threadIdx.x;
    if (e >= n_edges) return;
    int d = dst[e];
    int p = atomicAdd(&g_cursor[d], 1);
    g_edges[p] = make_int2(src[e], __float_as_int(ew[e]));
}

// ===========================================================================
// Gather: out[r] = sum_{e in CSR row r} w_e * h[src_e]   — no atomics.
// 16 lanes per row; unroll-4 for MLP against L2 latency.
// ===========================================================================
__global__ __launch_bounds__(256) void gather_kernel(
    float* __restrict__ out, int n_nodes)
{
    const int idx  = blockIdx.x * blockDim.x + threadIdx.x;
    const int row  = idx >> 4;
    const int lane = idx & 15;
    if (row >= n_nodes) return;

    const int start = g_starts[row];
    const int end   = start + g_counts[row];

    float4 acc = make_float4(0.f, 0.f, 0.f, 0.f);
    int j = start;

    for (; j + 4 <= end; j += 4) {
        int2 e0 = g_edges[j];
        int2 e1 = g_edges[j + 1];
        int2 e2 = g_edges[j + 2];
        int2 e3 = g_edges[j + 3];
        float4 h0 = *reinterpret_cast<const float4*>(&g_h[(size_t)e0.x * OUT_F + lane * 4]);
        float4 h1 = *reinterpret_cast<const float4*>(&g_h[(size_t)e1.x * OUT_F + lane * 4]);
        float4 h2 = *reinterpret_cast<const float4*>(&g_h[(size_t)e2.x * OUT_F + lane * 4]);
        float4 h3 = *reinterpret_cast<const float4*>(&g_h[(size_t)e3.x * OUT_F + lane * 4]);
        float w0 = __int_as_float(e0.y), w1 = __int_as_float(e1.y);
        float w2 = __int_as_float(e2.y), w3 = __int_as_float(e3.y);
        acc.x += w0 * h0.x;  acc.y += w0 * h0.y;  acc.z += w0 * h0.z;  acc.w += w0 * h0.w;
        acc.x += w1 * h1.x;  acc.y += w1 * h1.y;  acc.z += w1 * h1.z;  acc.w += w1 * h1.w;
        acc.x += w2 * h2.x;  acc.y += w2 * h2.y;  acc.z += w2 * h2.z;  acc.w += w2 * h2.w;
        acc.x += w3 * h3.x;  acc.y += w3 * h3.y;  acc.z += w3 * h3.z;  acc.w += w3 * h3.w;
    }
    for (; j < end; ++j) {
        int2 e = g_edges[j];
        float4 hv = *reinterpret_cast<const float4*>(&g_h[(size_t)e.x * OUT_F + lane * 4]);
        float w = __int_as_float(e.y);
        acc.x += w * hv.x;  acc.y += w * hv.y;  acc.z += w * hv.z;  acc.w += w * hv.w;
    }

    *reinterpret_cast<float4*>(&out[(size_t)row * OUT_F + lane * 4]) = acc;
}

// ===========================================================================
extern "C" void kernel_launch(void* const* d_in, const int* in_sizes, int n_in,
                              void* d_out, int out_size)
{
    const float* x   = (const float*)d_in[0];
    const int*   es  = (const int*)  d_in[1];
    const int*   ed  = (const int*)  d_in[2];
    const float* ew  = (const float*)d_in[3];
    const float* W   = (const float*)d_in[4];
    const float* b   = (const float*)d_in[5];
    float*       out = (float*)d_out;

    const int n_nodes = in_sizes[0] / IN_F;
    const int n_edges = in_sizes[1];
    const int eblk = (n_edges + 255) / 256;

    cudaFuncSetAttribute(gemm_mma_kernel,
                         cudaFuncAttributeMaxDynamicSharedMemorySize, SM_TOTAL);

    // GEMM (tensor-core mma.sync, bf16 3-term split)
    gemm_mma_kernel<<<(n_nodes + TILE_M - 1) / TILE_M, 256, SM_TOTAL>>>(x, W, b, n_nodes);

    // CSR build
    zero_counts_kernel<<<NB, SCAN_BS>>>();
    hist_kernel<<<eblk, 256>>>(ed, n_edges);
    scanA_kernel<<<NB, SCAN_BS>>>();
    scanB_kernel<<<1, 512>>>();
    scanC_kernel<<<NB, SCAN_BS>>>();
    fill_kernel<<<eblk, 256>>>(es, ed, ew, n_edges);

    // Gather (writes every output row exactly once)
    gather_kernel<<<(n_nodes * 16 + 255) / 256, 256>>>(out, n_nodes);
}